// round 14
// baseline (speedup 1.0000x reference)
#include <cuda_runtime.h>

#define T_LEN 131072
#define B_ROWS 96
#define CHUNK 64
#define WARM 32
#define CPR (T_LEN / CHUNK)                 /* 2048 chunks per row */
#define TPB 64
#define NWARP (TPB / 32)                    /* 2 */
#define CH_PER_WARP 128                     /* 4 chunks per lane, 2 streams */
#define WARPS_PER_ROW (CPR / CH_PER_WARP)   /* 16 */
#define TOTAL_WARPS (B_ROWS * WARPS_PER_ROW)/* 1536 */
#define GRID (TOTAL_WARPS / NWARP)          /* 768 */
#define WIN 32                              /* samples per window */
#define TILE_F4 (64 * 9)                    /* one stream tile: 9216 B */

// ---------------------------------------------------------------------------
// Compile-time Butterworth(6, wn=1/6): exact port of the reference numpy path.
// ---------------------------------------------------------------------------
constexpr double csqrt(double x) {
    double g = x;
    for (int i = 0; i < 200; ++i) g = 0.5 * (g + x / g);
    return g;
}
constexpr double SQ2 = csqrt(2.0);
constexpr double SQ3 = csqrt(3.0);
constexpr double SQ6 = csqrt(6.0);
constexpr double WRP = 4.0 * (2.0 - SQ3);          // 4*tan(pi/12)
constexpr double C12 = (SQ6 + SQ2) / 4.0;
constexpr double S12 = (SQ6 - SQ2) / 4.0;
constexpr double C45 = SQ2 / 2.0;

constexpr double P1R = -WRP * C12, P1I = WRP * S12;
constexpr double P2R = -WRP * C45, P2I = WRP * C45;
constexpr double P3R = -WRP * S12, P3I = WRP * C12;

constexpr double DEN1 = (4.0 - P1R) * (4.0 - P1R) + P1I * P1I;
constexpr double DEN2 = (4.0 - P2R) * (4.0 - P2R) + P2I * P2I;
constexpr double DEN3 = (4.0 - P3R) * (4.0 - P3R) + P3I * P3I;

constexpr double RZ1 = ((4.0 + P1R) * (4.0 - P1R) - P1I * P1I) / DEN1;
constexpr double IZ1 = 8.0 * P1I / DEN1;
constexpr double RZ2 = ((4.0 + P2R) * (4.0 - P2R) - P2I * P2I) / DEN2;
constexpr double IZ2 = 8.0 * P2I / DEN2;
constexpr double RZ3 = ((4.0 + P3R) * (4.0 - P3R) - P3I * P3I) / DEN3;
constexpr double IZ3 = 8.0 * P3I / DEN3;

constexpr double W2 = WRP * WRP;
constexpr double KZ = (W2 * W2 * W2) / (DEN1 * DEN2 * DEN3);

constexpr double CC1 = 2.0 * RZ1, MM1 = RZ1 * RZ1 + IZ1 * IZ1;
constexpr double CC2 = 2.0 * RZ2, MM2 = RZ2 * RZ2 + IZ2 * IZ2;
constexpr double CC3 = 2.0 * RZ3, MM3 = RZ3 * RZ3 + IZ3 * IZ3;

constexpr double Q0 = 1.0;
constexpr double Q1 = -(CC1 + CC2);
constexpr double Q2 = MM1 + MM2 + CC1 * CC2;
constexpr double Q3 = -(CC1 * MM2 + CC2 * MM1);
constexpr double Q4 = MM1 * MM2;
constexpr double A1 = Q1 - CC3 * Q0;
constexpr double A2 = Q2 - CC3 * Q1 + MM3 * Q0;
constexpr double A3 = Q3 - CC3 * Q2 + MM3 * Q1;
constexpr double A4 = Q4 - CC3 * Q3 + MM3 * Q2;
constexpr double A5 = -CC3 * Q4 + MM3 * Q3;
constexpr double A6 = MM3 * Q4;

constexpr float FB0 = (float)(KZ * 1.0);
constexpr float FB1 = (float)(KZ * 6.0);
constexpr float FB2 = (float)(KZ * 15.0);
constexpr float FB3 = (float)(KZ * 20.0);
constexpr float FNA1 = -(float)A1;
constexpr float FNA2 = -(float)A2;
constexpr float FNA3 = -(float)A3;
constexpr float FNA4 = -(float)A4;
constexpr float FNA5 = -(float)A5;
constexpr float FNA6 = -(float)A6;
constexpr float INV_TOTAL = (float)(1.0 / ((double)B_ROWS * (double)T_LEN));

// ---- packed f32x2 helpers (double used as b64 carrier) ----
__device__ __forceinline__ double ffma2(double a, double b, double c) {
    double r;
    asm("fma.rn.f32x2 %0, %1, %2, %3;" : "=d"(r) : "d"(a), "d"(b), "d"(c));
    return r;
}
__device__ __forceinline__ double fmul2(double a, double b) {
    double r;
    asm("mul.rn.f32x2 %0, %1, %2;" : "=d"(r) : "d"(a), "d"(b));
    return r;
}
__device__ __forceinline__ double pack2(float lo, float hi) {
    double r;
    asm("mov.b64 %0, {%1, %2};" : "=d"(r) : "f"(lo), "f"(hi));
    return r;
}
__device__ __forceinline__ void unpack2(double v, float& lo, float& hi) {
    asm("mov.b64 {%0, %1}, %2;" : "=f"(lo), "=f"(hi) : "d"(v));
}
__device__ __forceinline__ void absadd2(double& acc, double y) {
    asm("{\n\t"
        ".reg .b64 t;\n\t"
        "and.b64 t, %1, 0x7FFFFFFF7FFFFFFF;\n\t"
        "add.rn.f32x2 %0, %0, t;\n\t"
        "}" : "+d"(acc) : "d"(y));
}
__device__ __forceinline__ double clear_lo(double v) {
    double r;
    asm("and.b64 %0, %1, 0xFFFFFFFF00000000;" : "=d"(r) : "d"(v));
    return r;
}

// Scratch for single-kernel reduction (counter reset by finishing block).
__device__ float g_partials[GRID];
__device__ unsigned int g_done = 0;

__global__ void __launch_bounds__(TPB) lp_mae_kernel(
    const float* __restrict__ outp, const float* __restrict__ tgtp,
    float* __restrict__ result)
{
    // Per-warp: two stream tiles (A: chunks 0-63 of group, B: 64-127).
    __shared__ float4 tiles[NWARP][2 * TILE_F4];

    int lane = threadIdx.x & 31;
    int warp = threadIdx.x >> 5;
    int gwarp = blockIdx.x * NWARP + warp;
    int row = gwarp >> 4;                    // / WARPS_PER_ROW
    int wc  = gwarp & 15;                    // 128-chunk group within row
    int wbase = row * T_LEN + wc * (CH_PER_WARP * CHUNK);

    // R5/R11-validated staging mapping: 8 consecutive lanes cover one
    // contiguous 128B line.
    int sc  = lane >> 3;
    int st4 = lane & 7;
    int st4_4 = st4 * 4;
    int sbaseA = wbase + sc * CHUNK + st4_4;
    int sbaseB = sbaseA + 64 * CHUNK;

    float4* tileA = tiles[warp];
    float4* tileB = tiles[warp] + TILE_F4;
    int rowA = lane * 9;                     // lo chunk row (float4 units)
    int rowB = (lane + 32) * 9;              // hi chunk row

    // Shared packed coefficients (b-symmetry: b6=b0, b5=b1, b4=b2)
    const double cb0 = pack2(FB0, FB0), cb1 = pack2(FB1, FB1);
    const double cb2 = pack2(FB2, FB2), cb3 = pack2(FB3, FB3);
    const double ca1 = pack2(FNA1, FNA1), ca2 = pack2(FNA2, FNA2);
    const double ca3 = pack2(FNA3, FNA3), ca4 = pack2(FNA4, FNA4);
    const double ca5 = pack2(FNA5, FNA5), ca6 = pack2(FNA6, FNA6);

    const double dzero = pack2(0.f, 0.f);
    // Stream A state (chunks lane, lane+32)
    double zA0 = dzero, zA1 = dzero, zA2 = dzero, zA3 = dzero, zA4 = dzero, zA5 = dzero;
    // Stream B state (chunks lane+64, lane+96)
    double zB0 = dzero, zB1 = dzero, zB2 = dzero, zB3 = dzero, zB4 = dzero, zB5 = dzero;
    double sA = dzero, sB = dzero;
    double yA, yB;

#define STEP_A(XLO, XHI) do { \
        double x2_ = pack2((XLO), (XHI)); \
        yA  = ffma2(cb0, x2_, zA0); \
        zA0 = ffma2(ca1, yA, ffma2(cb1, x2_, zA1)); \
        zA1 = ffma2(ca2, yA, ffma2(cb2, x2_, zA2)); \
        zA2 = ffma2(ca3, yA, ffma2(cb3, x2_, zA3)); \
        zA3 = ffma2(ca4, yA, ffma2(cb2, x2_, zA4)); \
        zA4 = ffma2(ca5, yA, ffma2(cb1, x2_, zA5)); \
        zA5 = ffma2(ca6, yA, fmul2(cb0, x2_)); \
    } while (0)
#define STEP_B(XLO, XHI) do { \
        double x2_ = pack2((XLO), (XHI)); \
        yB  = ffma2(cb0, x2_, zB0); \
        zB0 = ffma2(ca1, yB, ffma2(cb1, x2_, zB1)); \
        zB1 = ffma2(ca2, yB, ffma2(cb2, x2_, zB2)); \
        zB2 = ffma2(ca3, yB, ffma2(cb3, x2_, zB3)); \
        zB3 = ffma2(ca4, yB, ffma2(cb2, x2_, zB4)); \
        zB4 = ffma2(ca5, yB, ffma2(cb1, x2_, zB5)); \
        zB5 = ffma2(ca6, yB, fmul2(cb0, x2_)); \
    } while (0)

#define STAGE(TILE, SBASE, TOFF, CLAMP) do { \
        _Pragma("unroll") \
        for (int j = 0; j < 16; ++j) { \
            int g = (SBASE) + (j * 4) * CHUNK + (TOFF); \
            if (CLAMP) g = max(g, st4_4); \
            float4 o = *(const float4*)(outp + g); \
            float4 t = *(const float4*)(tgtp + g); \
            (TILE)[(j * 4 + sc) * 9 + st4] = \
                make_float4(o.x - t.x, o.y - t.y, o.z - t.z, o.w - t.w); \
        } \
    } while (0)

    // ---- Warmup window (toff = -32): both streams, outputs discarded ----
    {
        bool needs_clamp = (wbase == 0);
        STAGE(tileA, sbaseA, -WIN, needs_clamp);
        STAGE(tileB, sbaseB, -WIN, false);
        __syncwarp();
        #pragma unroll
        for (int i = 0; i < 8; ++i) {
            float4 aA = tileA[rowA + i], bA = tileA[rowB + i];
            float4 aB = tileB[rowA + i], bB = tileB[rowB + i];
            STEP_A(aA.x, bA.x); STEP_B(aB.x, bB.x);
            STEP_A(aA.y, bA.y); STEP_B(aB.y, bB.y);
            STEP_A(aA.z, bA.z); STEP_B(aB.z, bB.z);
            STEP_A(aA.w, bA.w); STEP_B(aB.w, bB.w);
        }
        __syncwarp();
    }

    // Row's chunk 0 = stream A lo chain of lane 0 in the row's first group.
    if (wc == 0 && lane == 0) {
        zA0 = clear_lo(zA0); zA1 = clear_lo(zA1); zA2 = clear_lo(zA2);
        zA3 = clear_lo(zA3); zA4 = clear_lo(zA4); zA5 = clear_lo(zA5);
    }

    // ---- Main windows (toff = 0, +32): both streams, accumulate |y| ----
    #pragma unroll
    for (int w = 0; w < CHUNK / WIN; ++w) {
        int toff = w * WIN;
        STAGE(tileA, sbaseA, toff, false);
        STAGE(tileB, sbaseB, toff, false);
        __syncwarp();
        #pragma unroll
        for (int i = 0; i < 8; ++i) {
            float4 aA = tileA[rowA + i], bA = tileA[rowB + i];
            float4 aB = tileB[rowA + i], bB = tileB[rowB + i];
            STEP_A(aA.x, bA.x); STEP_B(aB.x, bB.x); absadd2(sA, yA); absadd2(sB, yB);
            STEP_A(aA.y, bA.y); STEP_B(aB.y, bB.y); absadd2(sA, yA); absadd2(sB, yB);
            STEP_A(aA.z, bA.z); STEP_B(aB.z, bB.z); absadd2(sA, yA); absadd2(sB, yB);
            STEP_A(aA.w, bA.w); STEP_B(aB.w, bB.w); absadd2(sA, yA); absadd2(sB, yB);
        }
        __syncwarp();
    }
#undef STEP_A
#undef STEP_B
#undef STAGE

    float slo, shi, tlo, thi;
    unpack2(sA, slo, shi);
    unpack2(sB, tlo, thi);
    float s = (slo + shi) + (tlo + thi);

    // Warp reduce
    #pragma unroll
    for (int off = 16; off; off >>= 1)
        s += __shfl_down_sync(0xffffffffu, s, off);

    __shared__ float ssum[NWARP];
    __shared__ int is_last;
    if (lane == 0) ssum[warp] = s;
    __syncthreads();
    if (threadIdx.x == 0) {
        g_partials[blockIdx.x] = ssum[0] + ssum[1];
        __threadfence();
        unsigned int t = atomicAdd(&g_done, 1u);
        is_last = (t == GRID - 1);
    }
    __syncthreads();

    // Last-arriving block: sum 768 partials (192 float4), write d_out.
    if (is_last) {
        const float4* p4 = (const float4*)g_partials;
        float v = 0.f;
        #pragma unroll
        for (int i = 0; i < GRID / 4 / TPB; ++i) {    // 3 float4 per thread
            float4 q = p4[threadIdx.x + i * TPB];
            v += (q.x + q.y) + (q.z + q.w);
        }
        #pragma unroll
        for (int off = 16; off; off >>= 1)
            v += __shfl_down_sync(0xffffffffu, v, off);
        if (lane == 0) ssum[warp] = v;
        __syncthreads();
        if (threadIdx.x == 0) {
            *result = (ssum[0] + ssum[1]) * INV_TOTAL;
            g_done = 0;
        }
    }
}

extern "C" void kernel_launch(void* const* d_in, const int* in_sizes, int n_in,
                              void* d_out, int out_size)
{
    (void)in_sizes; (void)n_in; (void)out_size;
    const float* outp = (const float*)d_in[0];
    const float* tgtp = (const float*)d_in[1];
    float* res = (float*)d_out;

    lp_mae_kernel<<<GRID, TPB>>>(outp, tgtp, res);
}

// round 15
// speedup vs baseline: 1.0111x; 1.0111x over previous
#include <cuda_runtime.h>

#define T_LEN 131072
#define B_ROWS 96
#define CHUNK 64
#define WARM 32
#define CPR (T_LEN / CHUNK)                 /* 2048 chunks per row */
#define TPB 128
#define NWARP (TPB / 32)                    /* 4 */
#define CH_PER_WARP 64                      /* 2 packed chunks per lane */
#define WARPS_PER_ROW (CPR / CH_PER_WARP)   /* 32 */
#define TOTAL_WARPS (B_ROWS * WARPS_PER_ROW)/* 3072 */
#define GRID (TOTAL_WARPS / NWARP)          /* 768 */
#define WIN 32                              /* samples per window */
#define TSTRIDE 9                           /* float4 row stride (validated) */

// ---------------------------------------------------------------------------
// Compile-time Butterworth(6, wn=1/6): exact port of the reference numpy path.
// ---------------------------------------------------------------------------
constexpr double csqrt(double x) {
    double g = x;
    for (int i = 0; i < 200; ++i) g = 0.5 * (g + x / g);
    return g;
}
constexpr double SQ2 = csqrt(2.0);
constexpr double SQ3 = csqrt(3.0);
constexpr double SQ6 = csqrt(6.0);
constexpr double WRP = 4.0 * (2.0 - SQ3);          // 4*tan(pi/12)
constexpr double C12 = (SQ6 + SQ2) / 4.0;
constexpr double S12 = (SQ6 - SQ2) / 4.0;
constexpr double C45 = SQ2 / 2.0;

constexpr double P1R = -WRP * C12, P1I = WRP * S12;
constexpr double P2R = -WRP * C45, P2I = WRP * C45;
constexpr double P3R = -WRP * S12, P3I = WRP * C12;

constexpr double DEN1 = (4.0 - P1R) * (4.0 - P1R) + P1I * P1I;
constexpr double DEN2 = (4.0 - P2R) * (4.0 - P2R) + P2I * P2I;
constexpr double DEN3 = (4.0 - P3R) * (4.0 - P3R) + P3I * P3I;

constexpr double RZ1 = ((4.0 + P1R) * (4.0 - P1R) - P1I * P1I) / DEN1;
constexpr double IZ1 = 8.0 * P1I / DEN1;
constexpr double RZ2 = ((4.0 + P2R) * (4.0 - P2R) - P2I * P2I) / DEN2;
constexpr double IZ2 = 8.0 * P2I / DEN2;
constexpr double RZ3 = ((4.0 + P3R) * (4.0 - P3R) - P3I * P3I) / DEN3;
constexpr double IZ3 = 8.0 * P3I / DEN3;

constexpr double W2 = WRP * WRP;
constexpr double KZ = (W2 * W2 * W2) / (DEN1 * DEN2 * DEN3);

constexpr double CC1 = 2.0 * RZ1, MM1 = RZ1 * RZ1 + IZ1 * IZ1;
constexpr double CC2 = 2.0 * RZ2, MM2 = RZ2 * RZ2 + IZ2 * IZ2;
constexpr double CC3 = 2.0 * RZ3, MM3 = RZ3 * RZ3 + IZ3 * IZ3;

constexpr double Q0 = 1.0;
constexpr double Q1 = -(CC1 + CC2);
constexpr double Q2 = MM1 + MM2 + CC1 * CC2;
constexpr double Q3 = -(CC1 * MM2 + CC2 * MM1);
constexpr double Q4 = MM1 * MM2;
constexpr double A1 = Q1 - CC3 * Q0;
constexpr double A2 = Q2 - CC3 * Q1 + MM3 * Q0;
constexpr double A3 = Q3 - CC3 * Q2 + MM3 * Q1;
constexpr double A4 = Q4 - CC3 * Q3 + MM3 * Q2;
constexpr double A5 = -CC3 * Q4 + MM3 * Q3;
constexpr double A6 = MM3 * Q4;

constexpr float FB0 = (float)(KZ * 1.0);
constexpr float FB1 = (float)(KZ * 6.0);
constexpr float FB2 = (float)(KZ * 15.0);
constexpr float FB3 = (float)(KZ * 20.0);
constexpr float FNA1 = -(float)A1;
constexpr float FNA2 = -(float)A2;
constexpr float FNA3 = -(float)A3;
constexpr float FNA4 = -(float)A4;
constexpr float FNA5 = -(float)A5;
constexpr float FNA6 = -(float)A6;
constexpr float INV_TOTAL = (float)(1.0 / ((double)B_ROWS * (double)T_LEN));

// ---- packed f32x2 helpers (double used as b64 carrier) ----
__device__ __forceinline__ double ffma2(double a, double b, double c) {
    double r;
    asm("fma.rn.f32x2 %0, %1, %2, %3;" : "=d"(r) : "d"(a), "d"(b), "d"(c));
    return r;
}
__device__ __forceinline__ double fmul2(double a, double b) {
    double r;
    asm("mul.rn.f32x2 %0, %1, %2;" : "=d"(r) : "d"(a), "d"(b));
    return r;
}
__device__ __forceinline__ double fsub2(double a, double b) {
    double r;
    asm("sub.rn.f32x2 %0, %1, %2;" : "=d"(r) : "d"(a), "d"(b));
    return r;
}
__device__ __forceinline__ double pack2(float lo, float hi) {
    double r;
    asm("mov.b64 %0, {%1, %2};" : "=d"(r) : "f"(lo), "f"(hi));
    return r;
}
__device__ __forceinline__ void unpack2(double v, float& lo, float& hi) {
    asm("mov.b64 {%0, %1}, %2;" : "=f"(lo), "=f"(hi) : "d"(v));
}
__device__ __forceinline__ void absadd2(double& acc, double y) {
    asm("{\n\t"
        ".reg .b64 t;\n\t"
        "and.b64 t, %1, 0x7FFFFFFF7FFFFFFF;\n\t"
        "add.rn.f32x2 %0, %0, t;\n\t"
        "}" : "+d"(acc) : "d"(y));
}
__device__ __forceinline__ double clear_lo(double v) {
    double r;
    asm("and.b64 %0, %1, 0xFFFFFFFF00000000;" : "=d"(r) : "d"(v));
    return r;
}

// Scratch for single-kernel reduction (counter reset by finishing block).
__device__ float g_partials[GRID];
__device__ unsigned int g_done = 0;

__global__ void __launch_bounds__(TPB) lp_mae_kernel(
    const float* __restrict__ outp, const float* __restrict__ tgtp,
    float* __restrict__ result)
{
    // Per-warp tile: 64 chunk-rows x (8 data float4 + 1 pad) = 9216B.
    __shared__ float4 tile4[NWARP][CH_PER_WARP * TSTRIDE];

    int lane = threadIdx.x & 31;
    int warp = threadIdx.x >> 5;
    int gwarp = blockIdx.x * NWARP + warp;
    int row = gwarp >> 5;                    // / WARPS_PER_ROW
    int wc  = gwarp & 31;                    // warp index within row
    int wbase = row * T_LEN + wc * (CH_PER_WARP * CHUNK);

    float4* mytile = tile4[warp];
    int rowA = lane * TSTRIDE;               // chunk lane (float4 units)
    int rowB = (lane + 32) * TSTRIDE;        // chunk lane+32

    // Validated staging mapping: sc = lane>>3 (sub-chunk 0..3),
    // st4 = lane&7 (float4 idx 0..7) -> 8 consecutive lanes cover one
    // contiguous 128B segment.
    int sc  = lane >> 3;
    int st4 = lane & 7;
    int sbase = wbase + sc * CHUNK + st4 * 4 - WARM;
    bool clamp = (wbase == 0);               // warp-uniform; row0/chunk0 head only

    // Packed coefficients (b-symmetry: b6=b0, b5=b1, b4=b2)
    const double cb0 = pack2(FB0, FB0), cb1 = pack2(FB1, FB1);
    const double cb2 = pack2(FB2, FB2), cb3 = pack2(FB3, FB3);
    const double ca1 = pack2(FNA1, FNA1), ca2 = pack2(FNA2, FNA2);
    const double ca3 = pack2(FNA3, FNA3), ca4 = pack2(FNA4, FNA4);
    const double ca5 = pack2(FNA5, FNA5), ca6 = pack2(FNA6, FNA6);

    const double dzero = pack2(0.f, 0.f);
    double z0 = dzero, z1 = dzero, z2 = dzero, z3 = dzero, z4 = dzero, z5 = dzero;
    double s2 = dzero;
    double y2;

    // Packed DF2T step (two independent chains per lane)
#define IIR_STEP2(XLO, XHI) do { \
        double x2_ = pack2((XLO), (XHI)); \
        y2 = ffma2(cb0, x2_, z0); \
        z0 = ffma2(ca1, y2, ffma2(cb1, x2_, z1)); \
        z1 = ffma2(ca2, y2, ffma2(cb2, x2_, z2)); \
        z2 = ffma2(ca3, y2, ffma2(cb3, x2_, z3)); \
        z3 = ffma2(ca4, y2, ffma2(cb2, x2_, z4)); \
        z4 = ffma2(ca5, y2, ffma2(cb1, x2_, z5)); \
        z5 = ffma2(ca6, y2, fmul2(cb0, x2_)); \
    } while (0)

    // Load window at TOFF into the 16-double2 register buffer P.
    // LDGs issue here and retire during the compute that follows (R10).
#define PREFETCH(TOFF, CLAMP) do { \
        _Pragma("unroll") \
        for (int j = 0; j < 16; ++j) { \
            int g = sbase + j * (4 * CHUNK) + (TOFF); \
            if (CLAMP) g = max(g, 0); \
            double2 o2_ = *(const double2*)(outp + g); \
            double2 t2_ = *(const double2*)(tgtp + g); \
            P[j].x = fsub2(o2_.x, t2_.x); \
            P[j].y = fsub2(o2_.y, t2_.y); \
        } \
    } while (0)

#define COMMIT() do { \
        _Pragma("unroll") \
        for (int j = 0; j < 16; ++j) \
            *(double2*)&mytile[(j * 4 + sc) * TSTRIDE + st4] = P[j]; \
        __syncwarp(); \
    } while (0)

    double2 P[16];

    // ---- Window 0 (warmup, toff=-32): prologue load, outputs discarded ----
    PREFETCH(-WIN, clamp);
    COMMIT();
    PREFETCH(0, false);                      // window 1 loads fly during warmup compute
    #pragma unroll
    for (int i = 0; i < 8; ++i) {
        float4 a = mytile[rowA + i];
        float4 b = mytile[rowB + i];
        IIR_STEP2(a.x, b.x);
        IIR_STEP2(a.y, b.y);
        IIR_STEP2(a.z, b.z);
        IIR_STEP2(a.w, b.w);
    }
    // Row's chunk 0 (lo chain of lane 0 in each row's first warp): zero init.
    if (wc == 0 && lane == 0) {
        z0 = clear_lo(z0); z1 = clear_lo(z1); z2 = clear_lo(z2);
        z3 = clear_lo(z3); z4 = clear_lo(z4); z5 = clear_lo(z5);
    }
    __syncwarp();

    // ---- Window 1 (main, toff=0) ----
    COMMIT();
    PREFETCH(WIN, false);                    // window 2 loads fly during compute
    #pragma unroll
    for (int i = 0; i < 8; ++i) {
        float4 a = mytile[rowA + i];
        float4 b = mytile[rowB + i];
        IIR_STEP2(a.x, b.x); absadd2(s2, y2);
        IIR_STEP2(a.y, b.y); absadd2(s2, y2);
        IIR_STEP2(a.z, b.z); absadd2(s2, y2);
        IIR_STEP2(a.w, b.w); absadd2(s2, y2);
    }
    __syncwarp();

    // ---- Window 2 (main, toff=+32) ----
    COMMIT();
    #pragma unroll
    for (int i = 0; i < 8; ++i) {
        float4 a = mytile[rowA + i];
        float4 b = mytile[rowB + i];
        IIR_STEP2(a.x, b.x); absadd2(s2, y2);
        IIR_STEP2(a.y, b.y); absadd2(s2, y2);
        IIR_STEP2(a.z, b.z); absadd2(s2, y2);
        IIR_STEP2(a.w, b.w); absadd2(s2, y2);
    }
#undef IIR_STEP2
#undef PREFETCH
#undef COMMIT

    float slo, shi;
    unpack2(s2, slo, shi);
    float s = slo + shi;

    // Warp reduce
    #pragma unroll
    for (int off = 16; off; off >>= 1)
        s += __shfl_down_sync(0xffffffffu, s, off);

    __shared__ float ssum[NWARP];
    __shared__ int is_last;
    if (lane == 0) ssum[warp] = s;
    __syncthreads();
    if (threadIdx.x == 0) {
        float tot = 0.f;
        #pragma unroll
        for (int i = 0; i < NWARP; ++i) tot += ssum[i];
        g_partials[blockIdx.x] = tot;
        __threadfence();
        unsigned int t = atomicAdd(&g_done, 1u);
        is_last = (t == GRID - 1);
    }
    __syncthreads();

    // Last-arriving block: sum all partials, write d_out, reset counter.
    if (is_last) {
        float v = 0.f;
        #pragma unroll
        for (int i = 0; i < GRID / TPB; ++i)      // 6 partials per thread
            v += g_partials[threadIdx.x + i * TPB];
        #pragma unroll
        for (int off = 16; off; off >>= 1)
            v += __shfl_down_sync(0xffffffffu, v, off);
        if (lane == 0) ssum[warp] = v;
        __syncthreads();
        if (threadIdx.x == 0) {
            float tot = 0.f;
            #pragma unroll
            for (int i = 0; i < NWARP; ++i) tot += ssum[i];
            *result = tot * INV_TOTAL;
            g_done = 0;                           // reset for next replay
        }
    }
}

extern "C" void kernel_launch(void* const* d_in, const int* in_sizes, int n_in,
                              void* d_out, int out_size)
{
    (void)in_sizes; (void)n_in; (void)out_size;
    const float* outp = (const float*)d_in[0];
    const float* tgtp = (const float*)d_in[1];
    float* res = (float*)d_out;

    lp_mae_kernel<<<GRID, TPB>>>(outp, tgtp, res);
}

// round 16
// speedup vs baseline: 1.1115x; 1.0992x over previous
#include <cuda_runtime.h>

#define T_LEN 131072
#define B_ROWS 96
#define CHUNK 64
#define WARM 32
#define CPR (T_LEN / CHUNK)                 /* 2048 chunks per row */
#define TPB 64                              /* 2 warps per block (balance play) */
#define NWARP (TPB / 32)                    /* 2 */
#define CH_PER_WARP 64                      /* 2 packed chunks per lane */
#define WARPS_PER_ROW (CPR / CH_PER_WARP)   /* 32 */
#define TOTAL_WARPS (B_ROWS * WARPS_PER_ROW)/* 3072 */
#define GRID (TOTAL_WARPS / NWARP)          /* 1536 */
#define WIN 32                              /* samples per main window */

// ---------------------------------------------------------------------------
// Compile-time Butterworth(6, wn=1/6): exact port of the reference numpy path.
// ---------------------------------------------------------------------------
constexpr double csqrt(double x) {
    double g = x;
    for (int i = 0; i < 200; ++i) g = 0.5 * (g + x / g);
    return g;
}
constexpr double SQ2 = csqrt(2.0);
constexpr double SQ3 = csqrt(3.0);
constexpr double SQ6 = csqrt(6.0);
constexpr double WRP = 4.0 * (2.0 - SQ3);          // 4*tan(pi/12)
constexpr double C12 = (SQ6 + SQ2) / 4.0;
constexpr double S12 = (SQ6 - SQ2) / 4.0;
constexpr double C45 = SQ2 / 2.0;

constexpr double P1R = -WRP * C12, P1I = WRP * S12;
constexpr double P2R = -WRP * C45, P2I = WRP * C45;
constexpr double P3R = -WRP * S12, P3I = WRP * C12;

constexpr double DEN1 = (4.0 - P1R) * (4.0 - P1R) + P1I * P1I;
constexpr double DEN2 = (4.0 - P2R) * (4.0 - P2R) + P2I * P2I;
constexpr double DEN3 = (4.0 - P3R) * (4.0 - P3R) + P3I * P3I;

constexpr double RZ1 = ((4.0 + P1R) * (4.0 - P1R) - P1I * P1I) / DEN1;
constexpr double IZ1 = 8.0 * P1I / DEN1;
constexpr double RZ2 = ((4.0 + P2R) * (4.0 - P2R) - P2I * P2I) / DEN2;
constexpr double IZ2 = 8.0 * P2I / DEN2;
constexpr double RZ3 = ((4.0 + P3R) * (4.0 - P3R) - P3I * P3I) / DEN3;
constexpr double IZ3 = 8.0 * P3I / DEN3;

constexpr double W2 = WRP * WRP;
constexpr double KZ = (W2 * W2 * W2) / (DEN1 * DEN2 * DEN3);

constexpr double CC1 = 2.0 * RZ1, MM1 = RZ1 * RZ1 + IZ1 * IZ1;
constexpr double CC2 = 2.0 * RZ2, MM2 = RZ2 * RZ2 + IZ2 * IZ2;
constexpr double CC3 = 2.0 * RZ3, MM3 = RZ3 * RZ3 + IZ3 * IZ3;

constexpr double Q0 = 1.0;
constexpr double Q1 = -(CC1 + CC2);
constexpr double Q2 = MM1 + MM2 + CC1 * CC2;
constexpr double Q3 = -(CC1 * MM2 + CC2 * MM1);
constexpr double Q4 = MM1 * MM2;
constexpr double A1 = Q1 - CC3 * Q0;
constexpr double A2 = Q2 - CC3 * Q1 + MM3 * Q0;
constexpr double A3 = Q3 - CC3 * Q2 + MM3 * Q1;
constexpr double A4 = Q4 - CC3 * Q3 + MM3 * Q2;
constexpr double A5 = -CC3 * Q4 + MM3 * Q3;
constexpr double A6 = MM3 * Q4;

constexpr float FB0 = (float)(KZ * 1.0);
constexpr float FB1 = (float)(KZ * 6.0);
constexpr float FB2 = (float)(KZ * 15.0);
constexpr float FB3 = (float)(KZ * 20.0);
constexpr float FB4 = (float)(KZ * 15.0);
constexpr float FB5 = (float)(KZ * 6.0);
constexpr float FB6 = (float)(KZ * 1.0);
constexpr float FNA1 = -(float)A1;
constexpr float FNA2 = -(float)A2;
constexpr float FNA3 = -(float)A3;
constexpr float FNA4 = -(float)A4;
constexpr float FNA5 = -(float)A5;
constexpr float FNA6 = -(float)A6;
constexpr float INV_TOTAL = (float)(1.0 / ((double)B_ROWS * (double)T_LEN));

// ---- packed f32x2 helpers (double used as b64 carrier) ----
__device__ __forceinline__ double ffma2(double a, double b, double c) {
    double r;
    asm("fma.rn.f32x2 %0, %1, %2, %3;" : "=d"(r) : "d"(a), "d"(b), "d"(c));
    return r;
}
__device__ __forceinline__ double fmul2(double a, double b) {
    double r;
    asm("mul.rn.f32x2 %0, %1, %2;" : "=d"(r) : "d"(a), "d"(b));
    return r;
}
__device__ __forceinline__ double pack2(float lo, float hi) {
    double r;
    asm("mov.b64 %0, {%1, %2};" : "=d"(r) : "f"(lo), "f"(hi));
    return r;
}
__device__ __forceinline__ void unpack2(double v, float& lo, float& hi) {
    asm("mov.b64 {%0, %1}, %2;" : "=f"(lo), "=f"(hi) : "d"(v));
}
__device__ __forceinline__ void absadd2(double& acc, double y) {
    asm("{\n\t"
        ".reg .b64 t;\n\t"
        "and.b64 t, %1, 0x7FFFFFFF7FFFFFFF;\n\t"
        "add.rn.f32x2 %0, %0, t;\n\t"
        "}" : "+d"(acc) : "d"(y));
}
__device__ __forceinline__ double clear_lo(double v) {
    double r;
    asm("and.b64 %0, %1, 0xFFFFFFFF00000000;" : "=d"(r) : "d"(v));
    return r;
}

// Scratch for single-kernel reduction (counter reset by finishing block).
__device__ float g_partials[GRID];
__device__ unsigned int g_done = 0;

__global__ void __launch_bounds__(TPB) lp_mae_kernel(
    const float* __restrict__ outp, const float* __restrict__ tgtp,
    float* __restrict__ result)
{
    // Per-warp tile: 64 chunk-rows x (8 data float4 + 1 pad float4) = 9216B.
    __shared__ float4 tile4[NWARP][CH_PER_WARP * 9];

    int lane = threadIdx.x & 31;
    int warp = threadIdx.x >> 5;
    int gwarp = blockIdx.x * NWARP + warp;
    int row = gwarp >> 5;                    // / WARPS_PER_ROW
    int wc  = gwarp & 31;                    // warp index within row
    int wbase = row * T_LEN + wc * (CH_PER_WARP * CHUNK);

    // Staging: lane -> (sub-chunk 0..3, float4 idx 0..7); 16 j-iters cover 64 rows.
    // 8 consecutive lanes cover one contiguous 128B line (validated).
    int sc  = lane >> 3;
    int st4 = lane & 7;
    int st4_4 = st4 * 4;
    int sbase = wbase + sc * CHUNK + st4_4;

    float4* mytile = tile4[warp];
    int rowA = lane * 9;                     // chunk lane
    int rowB = (lane + 32) * 9;              // chunk lane+32

    // Packed coefficients (both halves identical)
    const double cb0 = pack2(FB0, FB0), cb1 = pack2(FB1, FB1);
    const double cb2 = pack2(FB2, FB2), cb3 = pack2(FB3, FB3);
    const double cb4 = pack2(FB4, FB4), cb5 = pack2(FB5, FB5);
    const double cb6 = pack2(FB6, FB6);
    const double ca1 = pack2(FNA1, FNA1), ca2 = pack2(FNA2, FNA2);
    const double ca3 = pack2(FNA3, FNA3), ca4 = pack2(FNA4, FNA4);
    const double ca5 = pack2(FNA5, FNA5), ca6 = pack2(FNA6, FNA6);

    const double dzero = pack2(0.f, 0.f);
    double z0 = dzero, z1 = dzero, z2 = dzero, z3 = dzero, z4 = dzero, z5 = dzero;
    double s2 = dzero;
    double y2;

    // Packed DF2T step (two independent chains, lo=chunk lane, hi=chunk lane+32)
#define IIR_STEP2(XLO, XHI) do { \
        double x2_ = pack2((XLO), (XHI)); \
        y2 = ffma2(cb0, x2_, z0); \
        z0 = ffma2(ca1, y2, ffma2(cb1, x2_, z1)); \
        z1 = ffma2(ca2, y2, ffma2(cb2, x2_, z2)); \
        z2 = ffma2(ca3, y2, ffma2(cb3, x2_, z3)); \
        z3 = ffma2(ca4, y2, ffma2(cb4, x2_, z4)); \
        z4 = ffma2(ca5, y2, ffma2(cb5, x2_, z5)); \
        z5 = ffma2(ca6, y2, fmul2(cb6, x2_)); \
    } while (0)

#define STAGE(TOFF, CLAMP) do { \
        _Pragma("unroll") \
        for (int j = 0; j < 16; ++j) { \
            int g = sbase + (j * 4) * CHUNK + (TOFF); \
            if (CLAMP) g = max(g, st4_4); \
            float4 o = *(const float4*)(outp + g); \
            float4 t = *(const float4*)(tgtp + g); \
            mytile[(j * 4 + sc) * 9 + st4] = \
                make_float4(o.x - t.x, o.y - t.y, o.z - t.z, o.w - t.w); \
        } \
        __syncwarp(); \
    } while (0)

    // ---- Warmup window (toff = -32), outputs discarded ----
    {
        bool needs_clamp = (wbase == 0);
        STAGE(-WIN, needs_clamp);
        #pragma unroll
        for (int i = 0; i < 8; ++i) {
            float4 a = mytile[rowA + i];
            float4 b = mytile[rowB + i];
            IIR_STEP2(a.x, b.x);
            IIR_STEP2(a.y, b.y);
            IIR_STEP2(a.z, b.z);
            IIR_STEP2(a.w, b.w);
        }
        __syncwarp();
    }

    // Row's chunk 0 (lo half of lane 0 in each row's first warp): zero init.
    if (wc == 0 && lane == 0) {
        z0 = clear_lo(z0); z1 = clear_lo(z1); z2 = clear_lo(z2);
        z3 = clear_lo(z3); z4 = clear_lo(z4); z5 = clear_lo(z5);
    }

    // ---- Main windows (toff = 0, +32), accumulate |y| packed ----
    #pragma unroll
    for (int w = 0; w < CHUNK / WIN; ++w) {
        STAGE(w * WIN, false);
        #pragma unroll
        for (int i = 0; i < 8; ++i) {
            float4 a = mytile[rowA + i];
            float4 b = mytile[rowB + i];
            IIR_STEP2(a.x, b.x); absadd2(s2, y2);
            IIR_STEP2(a.y, b.y); absadd2(s2, y2);
            IIR_STEP2(a.z, b.z); absadd2(s2, y2);
            IIR_STEP2(a.w, b.w); absadd2(s2, y2);
        }
        __syncwarp();
    }
#undef IIR_STEP2
#undef STAGE

    float slo, shi;
    unpack2(s2, slo, shi);
    float s = slo + shi;

    // Warp reduce
    #pragma unroll
    for (int off = 16; off; off >>= 1)
        s += __shfl_down_sync(0xffffffffu, s, off);

    __shared__ float ssum[NWARP];
    __shared__ int is_last;
    if (lane == 0) ssum[warp] = s;
    __syncthreads();
    if (threadIdx.x == 0) {
        g_partials[blockIdx.x] = ssum[0] + ssum[1];
        __threadfence();
        unsigned int t = atomicAdd(&g_done, 1u);
        is_last = (t == GRID - 1);
    }
    __syncthreads();

    // Last-arriving block: sum 1536 partials (384 float4), write d_out.
    if (is_last) {
        const float4* p4 = (const float4*)g_partials;
        float v = 0.f;
        #pragma unroll
        for (int i = 0; i < GRID / 4 / TPB; ++i) {    // 6 float4 per thread
            float4 q = p4[threadIdx.x + i * TPB];
            v += (q.x + q.y) + (q.z + q.w);
        }
        #pragma unroll
        for (int off = 16; off; off >>= 1)
            v += __shfl_down_sync(0xffffffffu, v, off);
        if (lane == 0) ssum[warp] = v;
        __syncthreads();
        if (threadIdx.x == 0) {
            *result = (ssum[0] + ssum[1]) * INV_TOTAL;
            g_done = 0;                               // reset for next replay
        }
    }
}

extern "C" void kernel_launch(void* const* d_in, const int* in_sizes, int n_in,
                              void* d_out, int out_size)
{
    (void)in_sizes; (void)n_in; (void)out_size;
    const float* outp = (const float*)d_in[0];
    const float* tgtp = (const float*)d_in[1];
    float* res = (float*)d_out;

    lp_mae_kernel<<<GRID, TPB>>>(outp, tgtp, res);
}